// round 1
// baseline (speedup 1.0000x reference)
#include <cuda_runtime.h>
#include <cstdint>

// ---------------------------------------------------------------------------
// GCN layer: out = relu( spmm(x) @ W + b )
//   x:        [B, N, 128] f32     (d_in[0])
//   edge_row: [E] i32             (d_in[1])
//   edge_col: [E] i32             (d_in[2])
//   edge_vals:[E] f32             (d_in[3])
//   W:        [128, 128] f32      (d_in[4])
//   b:        [128] f32           (d_in[5])
//   out:      [B, N, 128] f32
// Plan: zero scratch agg -> atomic SpMM (red.global.add.v4.f32) -> fp32x2 GEMM
// with fused bias+relu epilogue.
// ---------------------------------------------------------------------------

#define C_DIM 128
static constexpr int  N_NODES   = 50000;
static constexpr long AGG_ELEMS = 4L * N_NODES * C_DIM;   // B=4 -> 25.6M floats

__device__ float g_agg[AGG_ELEMS];

// ---------------------------------------------------------------------------
// f32x2 packed helpers (Blackwell packed fp32 pipe; PTX-only, ptxas won't fuse)
// ---------------------------------------------------------------------------
__device__ __forceinline__ unsigned long long pack2(float lo, float hi) {
    unsigned long long r;
    asm("mov.b64 %0, {%1, %2};" : "=l"(r) : "f"(lo), "f"(hi));
    return r;
}
__device__ __forceinline__ void unpack2(unsigned long long p, float& lo, float& hi) {
    asm("mov.b64 {%0, %1}, %2;" : "=f"(lo), "=f"(hi) : "l"(p));
}
__device__ __forceinline__ void fma2(unsigned long long& d,
                                     unsigned long long a,
                                     unsigned long long b) {
    asm("fma.rn.f32x2 %0, %1, %2, %0;" : "+l"(d) : "l"(a), "l"(b));
}

// ---------------------------------------------------------------------------
// Kernel 1: zero the scratch accumulator (float4 grid-stride)
// ---------------------------------------------------------------------------
__global__ void zero_agg_kernel(long n4) {
    float4* p = reinterpret_cast<float4*>(g_agg);
    long i      = (long)blockIdx.x * blockDim.x + threadIdx.x;
    long stride = (long)gridDim.x * blockDim.x;
    const float4 z = make_float4(0.f, 0.f, 0.f, 0.f);
    for (; i < n4; i += stride) p[i] = z;
}

// ---------------------------------------------------------------------------
// Kernel 2: SpMM scatter-add. One warp per (edge, batch); each lane moves a
// float4 (32 lanes x 16B = 512B row). 4 edges per warp to amortize CTA count.
// blockIdx.y = batch -> batch-major CTA dispatch keeps per-batch x slice
// (25.6MB) L2-resident.
// ---------------------------------------------------------------------------
__global__ void __launch_bounds__(256)
spmm_kernel(const float* __restrict__ x,
            const int*   __restrict__ er,
            const int*   __restrict__ ec,
            const float* __restrict__ ev,
            int E, int N) {
    const int lane = threadIdx.x & 31;
    const int warp = threadIdx.x >> 5;
    const int b    = blockIdx.y;

    const float* xb   = x     + (size_t)b * N * C_DIM;
    float*       aggb = g_agg + (size_t)b * N * C_DIM;

    const int e0 = (blockIdx.x * 8 + warp) * 4;
#pragma unroll
    for (int i = 0; i < 4; ++i) {
        const int e = e0 + i;
        if (e >= E) break;
        const int   row = __ldg(er + e);
        const int   col = __ldg(ec + e);
        const float v   = __ldg(ev + e);

        const float4 xv = __ldg(reinterpret_cast<const float4*>(
                                    xb + (size_t)col * C_DIM) + lane);
        const float4 m  = make_float4(v * xv.x, v * xv.y, v * xv.z, v * xv.w);

        float* dst = aggb + (size_t)row * C_DIM + lane * 4;
        asm volatile("red.global.add.v4.f32 [%0], {%1, %2, %3, %4};"
                     :: "l"(dst), "f"(m.x), "f"(m.y), "f"(m.z), "f"(m.w)
                     : "memory");
    }
}

// ---------------------------------------------------------------------------
// Kernel 3: out = relu(agg @ W + bias)
// CTA tile: 128 rows x 128 cols. 256 threads, each an 8x8 micro-tile, with
// packed fp32x2 FMAs over column pairs. A-tile + full W in smem (128KB).
// ---------------------------------------------------------------------------
__global__ void __launch_bounds__(256)
gemm_kernel(const float* __restrict__ W,
            const float* __restrict__ bias,
            float*       __restrict__ out,
            int total_rows) {
    extern __shared__ float sm[];
    float* As = sm;                 // [128][128]
    float* Ws = sm + 128 * 128;     // [128][128]

    const int  tid  = threadIdx.x;
    const long row0 = (long)blockIdx.x * 128;

    // Load W tile (16384 floats = 4096 float4)
    {
        const float4* Wg = reinterpret_cast<const float4*>(W);
        float4*       Wd = reinterpret_cast<float4*>(Ws);
        for (int i = tid; i < 4096; i += 256) Wd[i] = Wg[i];
    }
    // Load A tile with row guard
    {
        const float4* Ag = reinterpret_cast<const float4*>(g_agg);
        float4*       Ad = reinterpret_cast<float4*>(As);
        for (int i = tid; i < 4096; i += 256) {
            const int  r  = i >> 5;         // /32
            const int  c4 = i & 31;
            const long gr = row0 + r;
            Ad[i] = (gr < total_rows) ? Ag[gr * 32 + c4]
                                      : make_float4(0.f, 0.f, 0.f, 0.f);
        }
    }

    const int tx = tid & 15;   // col group: cols [tx*8, tx*8+8)
    const int ty = tid >> 4;   // row group: rows [ty*8, ty*8+8)

    // Preload bias for this thread's 8 columns
    float bias_r[8];
#pragma unroll
    for (int c = 0; c < 8; ++c) bias_r[c] = __ldg(bias + tx * 8 + c);

    __syncthreads();

    unsigned long long acc[8][4];
#pragma unroll
    for (int r = 0; r < 8; ++r)
#pragma unroll
        for (int cp = 0; cp < 4; ++cp) acc[r][cp] = 0ULL;

    const float* a_base = As + ty * 8 * 128;

#pragma unroll 4
    for (int k = 0; k < 128; ++k) {
        const unsigned long long* wp =
            reinterpret_cast<const unsigned long long*>(Ws + k * 128 + tx * 8);
        const unsigned long long w0 = wp[0];
        const unsigned long long w1 = wp[1];
        const unsigned long long w2 = wp[2];
        const unsigned long long w3 = wp[3];
#pragma unroll
        for (int r = 0; r < 8; ++r) {
            const float a = a_base[r * 128 + k];
            const unsigned long long aa = pack2(a, a);
            fma2(acc[r][0], aa, w0);
            fma2(acc[r][1], aa, w1);
            fma2(acc[r][2], aa, w2);
            fma2(acc[r][3], aa, w3);
        }
    }

    // Epilogue: bias + relu + store
#pragma unroll
    for (int r = 0; r < 8; ++r) {
        const long gr = row0 + ty * 8 + r;
        if (gr >= total_rows) continue;
        float o[8];
#pragma unroll
        for (int cp = 0; cp < 4; ++cp)
            unpack2(acc[r][cp], o[2 * cp], o[2 * cp + 1]);
#pragma unroll
        for (int c = 0; c < 8; ++c)
            o[c] = fmaxf(o[c] + bias_r[c], 0.f);

        float4* op = reinterpret_cast<float4*>(out + gr * C_DIM + tx * 8);
        op[0] = make_float4(o[0], o[1], o[2], o[3]);
        op[1] = make_float4(o[4], o[5], o[6], o[7]);
    }
}

// ---------------------------------------------------------------------------
// Launch
// ---------------------------------------------------------------------------
extern "C" void kernel_launch(void* const* d_in, const int* in_sizes, int n_in,
                              void* d_out, int out_size) {
    const float* x    = (const float*)d_in[0];
    const int*   er   = (const int*)  d_in[1];
    const int*   ec   = (const int*)  d_in[2];
    const float* ev   = (const float*)d_in[3];
    const float* W    = (const float*)d_in[4];
    const float* bias = (const float*)d_in[5];
    float*       out  = (float*)d_out;

    const int E  = in_sizes[1];
    const int C  = in_sizes[5];            // 128
    const int BN = in_sizes[0] / C;        // B*N = 200000
    const int N  = N_NODES;
    const int B  = BN / N;

    // 1) zero scratch accumulator
    const long n4 = (long)BN * C / 4;
    zero_agg_kernel<<<1184, 256>>>(n4);

    // 2) SpMM scatter-add: grid.x over edge groups (32 edges/CTA), grid.y = batch
    dim3 sgrid((E + 31) / 32, B);
    spmm_kernel<<<sgrid, 256>>>(x, er, ec, ev, E, N);

    // 3) GEMM + bias + relu (128KB dynamic smem)
    cudaFuncSetAttribute(gemm_kernel,
                         cudaFuncAttributeMaxDynamicSharedMemorySize, 131072);
    gemm_kernel<<<(BN + 127) / 128, 256, 131072>>>(W, bias, out, BN);
}

// round 2
// speedup vs baseline: 1.2142x; 1.2142x over previous
#include <cuda_runtime.h>
#include <cstdint>

// ---------------------------------------------------------------------------
// GCN layer: out = relu( (A x) @ W + b )  ==  relu( A (x@W) + b )
//   x: [B,N,128] f32, edges (row,col,val) [E], W [128,128], b [128]
// Plan:
//   1) CSR build (zero deg -> histogram -> scan -> scatter packed {col,val})
//   2) y = x @ W   (fp32x2 tiled GEMM, no epilogue)  -> scratch g_y
//   3) gather: out[b,r] = relu( b + sum_e v_e * y[b, col_e] )   (no atomics)
// ---------------------------------------------------------------------------

#define C_DIM 128
static constexpr int  N_NODES = 50000;
static constexpr int  B_MAX   = 4;
static constexpr int  E_MAX   = 800000;
static constexpr long Y_ELEMS = (long)B_MAX * N_NODES * C_DIM;

__device__ float              g_y[Y_ELEMS];          // 102.4 MB scratch (x@W)
__device__ int                g_deg[N_NODES];
__device__ int                g_off[N_NODES + 1];
__device__ int                g_cur[N_NODES];
__device__ unsigned long long g_ebuf[E_MAX];         // packed {val:hi32, col:lo32}

// ---------------------------------------------------------------------------
// f32x2 packed helpers
// ---------------------------------------------------------------------------
__device__ __forceinline__ unsigned long long pack2(float lo, float hi) {
    unsigned long long r;
    asm("mov.b64 %0, {%1, %2};" : "=l"(r) : "f"(lo), "f"(hi));
    return r;
}
__device__ __forceinline__ void unpack2(unsigned long long p, float& lo, float& hi) {
    asm("mov.b64 {%0, %1}, %2;" : "=f"(lo), "=f"(hi) : "l"(p));
}
__device__ __forceinline__ void fma2(unsigned long long& d,
                                     unsigned long long a,
                                     unsigned long long b) {
    asm("fma.rn.f32x2 %0, %1, %2, %0;" : "+l"(d) : "l"(a), "l"(b));
}

// ---------------------------------------------------------------------------
// CSR build
// ---------------------------------------------------------------------------
__global__ void zero_deg_kernel(int n) {
    int i = blockIdx.x * blockDim.x + threadIdx.x;
    if (i < n) g_deg[i] = 0;
}

__global__ void hist_kernel(const int* __restrict__ er, int E) {
    int e = blockIdx.x * blockDim.x + threadIdx.x;
    if (e < E) atomicAdd(&g_deg[er[e]], 1);
}

// Single-CTA scan over N degrees -> g_off (exclusive, g_off[N]=E) and g_cur.
__global__ void __launch_bounds__(1024) scan_kernel(int N) {
    __shared__ int part[1024];
    const int tid   = threadIdx.x;
    const int chunk = (N + 1023) / 1024;
    const int s = tid * chunk;
    const int e = min(s + chunk, N);

    int sum = 0;
    for (int i = s; i < e; ++i) sum += g_deg[i];
    part[tid] = sum;
    __syncthreads();

    // Hillis-Steele inclusive scan
    for (int ofs = 1; ofs < 1024; ofs <<= 1) {
        int v = (tid >= ofs) ? part[tid - ofs] : 0;
        __syncthreads();
        part[tid] += v;
        __syncthreads();
    }
    int run = (tid == 0) ? 0 : part[tid - 1];
    for (int i = s; i < e; ++i) {
        g_off[i] = run;
        g_cur[i] = run;
        run += g_deg[i];
    }
    if (s < N && e == N) g_off[N] = run;
}

__global__ void scatter_kernel(const int*   __restrict__ er,
                               const int*   __restrict__ ec,
                               const float* __restrict__ ev,
                               int E) {
    int e = blockIdx.x * blockDim.x + threadIdx.x;
    if (e >= E) return;
    const int pos = atomicAdd(&g_cur[er[e]], 1);
    const unsigned long long rec =
        ((unsigned long long)__float_as_uint(ev[e]) << 32) | (unsigned)ec[e];
    g_ebuf[pos] = rec;
}

// ---------------------------------------------------------------------------
// GEMM: y = x @ W   (128x128 CTA tile, 256 threads, 8x8 micro-tile, fp32x2)
// ---------------------------------------------------------------------------
__global__ void __launch_bounds__(256)
gemm_kernel(const float* __restrict__ x,
            const float* __restrict__ W,
            int total_rows) {
    extern __shared__ float sm[];
    float* As = sm;                 // [128][128]
    float* Ws = sm + 128 * 128;     // [128][128]

    const int  tid  = threadIdx.x;
    const long row0 = (long)blockIdx.x * 128;

    {
        const float4* Wg = reinterpret_cast<const float4*>(W);
        float4*       Wd = reinterpret_cast<float4*>(Ws);
        for (int i = tid; i < 4096; i += 256) Wd[i] = Wg[i];
    }
    {
        const float4* Ag = reinterpret_cast<const float4*>(x);
        float4*       Ad = reinterpret_cast<float4*>(As);
        for (int i = tid; i < 4096; i += 256) {
            const int  r  = i >> 5;
            const int  c4 = i & 31;
            const long gr = row0 + r;
            Ad[i] = (gr < total_rows) ? Ag[gr * 32 + c4]
                                      : make_float4(0.f, 0.f, 0.f, 0.f);
        }
    }
    __syncthreads();

    const int tx = tid & 15;   // cols [tx*8, tx*8+8)
    const int ty = tid >> 4;   // rows [ty*8, ty*8+8)

    unsigned long long acc[8][4];
#pragma unroll
    for (int r = 0; r < 8; ++r)
#pragma unroll
        for (int cp = 0; cp < 4; ++cp) acc[r][cp] = 0ULL;

    const float* a_base = As + ty * 8 * 128;

#pragma unroll 4
    for (int k = 0; k < 128; ++k) {
        const unsigned long long* wp =
            reinterpret_cast<const unsigned long long*>(Ws + k * 128 + tx * 8);
        const unsigned long long w0 = wp[0];
        const unsigned long long w1 = wp[1];
        const unsigned long long w2 = wp[2];
        const unsigned long long w3 = wp[3];
#pragma unroll
        for (int r = 0; r < 8; ++r) {
            const float a = a_base[r * 128 + k];
            const unsigned long long aa = pack2(a, a);
            fma2(acc[r][0], aa, w0);
            fma2(acc[r][1], aa, w1);
            fma2(acc[r][2], aa, w2);
            fma2(acc[r][3], aa, w3);
        }
    }

#pragma unroll
    for (int r = 0; r < 8; ++r) {
        const long gr = row0 + ty * 8 + r;
        if (gr >= total_rows) continue;
        float o[8];
#pragma unroll
        for (int cp = 0; cp < 4; ++cp)
            unpack2(acc[r][cp], o[2 * cp], o[2 * cp + 1]);
        float4* op = reinterpret_cast<float4*>(g_y + gr * C_DIM + tx * 8);
        op[0] = make_float4(o[0], o[1], o[2], o[3]);
        op[1] = make_float4(o[4], o[5], o[6], o[7]);
    }
}

// ---------------------------------------------------------------------------
// Gather: out[b,n,:] = relu( bias + sum_e val_e * y[b, col_e, :] )
// One warp per row; lane owns 4 channels (float4). Edge records broadcast
// via shfl. 64 rows per CTA (8 warps x 8 rows), blockIdx.y = batch.
// ---------------------------------------------------------------------------
__global__ void __launch_bounds__(256)
gather_kernel(const float* __restrict__ bias,
              float*       __restrict__ out,
              int N) {
    const int lane = threadIdx.x & 31;
    const int warp = threadIdx.x >> 5;
    const int b    = blockIdx.y;

    const float4* yb    = reinterpret_cast<const float4*>(g_y) + (size_t)b * N * 32;
    const float4  bias4 = __ldg(reinterpret_cast<const float4*>(bias) + lane);

    const int n_base = blockIdx.x * 64;

#pragma unroll 1
    for (int i = 0; i < 8; ++i) {
        const int n = n_base + warp * 8 + i;
        if (n >= N) return;

        const int st = __ldg(&g_off[n]);
        const int en = __ldg(&g_off[n + 1]);

        float4 a0 = make_float4(0.f, 0.f, 0.f, 0.f);
        float4 a1 = make_float4(0.f, 0.f, 0.f, 0.f);

        for (int base = st; base < en; base += 32) {
            const int m = min(32, en - base);
            unsigned long long pk = 0;
            if (lane < m) pk = __ldg(&g_ebuf[base + lane]);

            int j = 0;
            for (; j + 1 < m; j += 2) {
                const unsigned long long p0 = __shfl_sync(0xffffffffu, pk, j);
                const unsigned long long p1 = __shfl_sync(0xffffffffu, pk, j + 1);
                const int   c0 = (int)(p0 & 0xffffffffu);
                const int   c1 = (int)(p1 & 0xffffffffu);
                const float v0 = __uint_as_float((unsigned)(p0 >> 32));
                const float v1 = __uint_as_float((unsigned)(p1 >> 32));
                const float4 x0 = __ldg(yb + (size_t)c0 * 32 + lane);
                const float4 x1 = __ldg(yb + (size_t)c1 * 32 + lane);
                a0.x = fmaf(v0, x0.x, a0.x); a0.y = fmaf(v0, x0.y, a0.y);
                a0.z = fmaf(v0, x0.z, a0.z); a0.w = fmaf(v0, x0.w, a0.w);
                a1.x = fmaf(v1, x1.x, a1.x); a1.y = fmaf(v1, x1.y, a1.y);
                a1.z = fmaf(v1, x1.z, a1.z); a1.w = fmaf(v1, x1.w, a1.w);
            }
            if (j < m) {
                const unsigned long long p0 = __shfl_sync(0xffffffffu, pk, j);
                const int   c0 = (int)(p0 & 0xffffffffu);
                const float v0 = __uint_as_float((unsigned)(p0 >> 32));
                const float4 x0 = __ldg(yb + (size_t)c0 * 32 + lane);
                a0.x = fmaf(v0, x0.x, a0.x); a0.y = fmaf(v0, x0.y, a0.y);
                a0.z = fmaf(v0, x0.z, a0.z); a0.w = fmaf(v0, x0.w, a0.w);
            }
        }

        float4 r;
        r.x = fmaxf(a0.x + a1.x + bias4.x, 0.f);
        r.y = fmaxf(a0.y + a1.y + bias4.y, 0.f);
        r.z = fmaxf(a0.z + a1.z + bias4.z, 0.f);
        r.w = fmaxf(a0.w + a1.w + bias4.w, 0.f);

        reinterpret_cast<float4*>(out)[((size_t)b * N + n) * 32 + lane] = r;
    }
}

// ---------------------------------------------------------------------------
// Launch
// ---------------------------------------------------------------------------
extern "C" void kernel_launch(void* const* d_in, const int* in_sizes, int n_in,
                              void* d_out, int out_size) {
    const float* x    = (const float*)d_in[0];
    const int*   er   = (const int*)  d_in[1];
    const int*   ec   = (const int*)  d_in[2];
    const float* ev   = (const float*)d_in[3];
    const float* W    = (const float*)d_in[4];
    const float* bias = (const float*)d_in[5];
    float*       out  = (float*)d_out;

    const int E  = in_sizes[1];
    const int C  = in_sizes[5];            // 128
    const int BN = in_sizes[0] / C;        // B*N
    const int N  = N_NODES;
    const int B  = BN / N;

    // 1) CSR build
    zero_deg_kernel<<<(N + 255) / 256, 256>>>(N);
    hist_kernel<<<(E + 255) / 256, 256>>>(er, E);
    scan_kernel<<<1, 1024>>>(N);
    scatter_kernel<<<(E + 255) / 256, 256>>>(er, ec, ev, E);

    // 2) y = x @ W
    cudaFuncSetAttribute(gemm_kernel,
                         cudaFuncAttributeMaxDynamicSharedMemorySize, 131072);
    gemm_kernel<<<(BN + 127) / 128, 256, 131072>>>(x, W, BN);

    // 3) gather + bias + relu
    dim3 ggrid((N + 63) / 64, B);
    gather_kernel<<<ggrid, 256>>>(bias, out, N);
}

// round 3
// speedup vs baseline: 1.2147x; 1.0005x over previous
#include <cuda_runtime.h>
#include <cstdint>

// ---------------------------------------------------------------------------
// GCN layer: out = relu( (A x) @ W + b )  ==  relu( A (x@W) + b )
//   x: [B,N,128] f32, edges (row,col,val) [E], W [128,128], b [128]
// Plan:
//   1) CSR build (zero deg -> histogram -> scan -> scatter packed {col,val})
//   2) y = x @ W   (fp32x2 tiled GEMM, no epilogue)  -> scratch g_y
//   3) gather: out[b,r] = relu( b + sum_e v_e * y[b, col_e] )   (no atomics)
// ---------------------------------------------------------------------------

#define C_DIM 128
static constexpr int  N_NODES = 50000;
static constexpr int  B_MAX   = 4;
static constexpr int  E_MAX   = 800000;
static constexpr long Y_ELEMS = (long)B_MAX * N_NODES * C_DIM;

__device__ float              g_y[Y_ELEMS];          // 102.4 MB scratch (x@W)
__device__ int                g_deg[N_NODES];
__device__ int                g_off[N_NODES + 1];
__device__ int                g_cur[N_NODES];
__device__ unsigned long long g_ebuf[E_MAX];         // packed {val:hi32, col:lo32}

// ---------------------------------------------------------------------------
// f32x2 packed helpers
// ---------------------------------------------------------------------------
__device__ __forceinline__ unsigned long long pack2(float lo, float hi) {
    unsigned long long r;
    asm("mov.b64 %0, {%1, %2};" : "=l"(r) : "f"(lo), "f"(hi));
    return r;
}
__device__ __forceinline__ void unpack2(unsigned long long p, float& lo, float& hi) {
    asm("mov.b64 {%0, %1}, %2;" : "=f"(lo), "=f"(hi) : "l"(p));
}
__device__ __forceinline__ void fma2(unsigned long long& d,
                                     unsigned long long a,
                                     unsigned long long b) {
    asm("fma.rn.f32x2 %0, %1, %2, %0;" : "+l"(d) : "l"(a), "l"(b));
}

// ---------------------------------------------------------------------------
// CSR build
// ---------------------------------------------------------------------------
__global__ void zero_deg_kernel(int n) {
    int i = blockIdx.x * blockDim.x + threadIdx.x;
    if (i < n) g_deg[i] = 0;
}

__global__ void hist_kernel(const int* __restrict__ er, int E) {
    int e = blockIdx.x * blockDim.x + threadIdx.x;
    if (e < E) atomicAdd(&g_deg[er[e]], 1);
}

// Single-CTA scan over N degrees -> g_off (exclusive, g_off[N]=E) and g_cur.
__global__ void __launch_bounds__(1024) scan_kernel(int N) {
    __shared__ int part[1024];
    const int tid   = threadIdx.x;
    const int chunk = (N + 1023) / 1024;
    const int s = tid * chunk;
    const int e = min(s + chunk, N);

    int sum = 0;
    for (int i = s; i < e; ++i) sum += g_deg[i];
    part[tid] = sum;
    __syncthreads();

    // Hillis-Steele inclusive scan
    for (int ofs = 1; ofs < 1024; ofs <<= 1) {
        int v = (tid >= ofs) ? part[tid - ofs] : 0;
        __syncthreads();
        part[tid] += v;
        __syncthreads();
    }
    int run = (tid == 0) ? 0 : part[tid - 1];
    for (int i = s; i < e; ++i) {
        g_off[i] = run;
        g_cur[i] = run;
        run += g_deg[i];
    }
    if (s < N && e == N) g_off[N] = run;
}

__global__ void scatter_kernel(const int*   __restrict__ er,
                               const int*   __restrict__ ec,
                               const float* __restrict__ ev,
                               int E) {
    int e = blockIdx.x * blockDim.x + threadIdx.x;
    if (e >= E) return;
    const int pos = atomicAdd(&g_cur[er[e]], 1);
    const unsigned long long rec =
        ((unsigned long long)__float_as_uint(ev[e]) << 32) | (unsigned)ec[e];
    g_ebuf[pos] = rec;
}

// ---------------------------------------------------------------------------
// GEMM: y = x @ W   (128x128 CTA tile, 256 threads, 8x8 micro-tile, fp32x2)
// ---------------------------------------------------------------------------
__global__ void __launch_bounds__(256)
gemm_kernel(const float* __restrict__ x,
            const float* __restrict__ W,
            int total_rows) {
    extern __shared__ float sm[];
    float* As = sm;                 // [128][128]
    float* Ws = sm + 128 * 128;     // [128][128]

    const int  tid  = threadIdx.x;
    const long row0 = (long)blockIdx.x * 128;

    {
        const float4* Wg = reinterpret_cast<const float4*>(W);
        float4*       Wd = reinterpret_cast<float4*>(Ws);
        for (int i = tid; i < 4096; i += 256) Wd[i] = Wg[i];
    }
    {
        const float4* Ag = reinterpret_cast<const float4*>(x);
        float4*       Ad = reinterpret_cast<float4*>(As);
        for (int i = tid; i < 4096; i += 256) {
            const int  r  = i >> 5;
            const int  c4 = i & 31;
            const long gr = row0 + r;
            Ad[i] = (gr < total_rows) ? Ag[gr * 32 + c4]
                                      : make_float4(0.f, 0.f, 0.f, 0.f);
        }
    }
    __syncthreads();

    const int tx = tid & 15;   // cols [tx*8, tx*8+8)
    const int ty = tid >> 4;   // rows [ty*8, ty*8+8)

    unsigned long long acc[8][4];
#pragma unroll
    for (int r = 0; r < 8; ++r)
#pragma unroll
        for (int cp = 0; cp < 4; ++cp) acc[r][cp] = 0ULL;

    const float* a_base = As + ty * 8 * 128;

#pragma unroll 4
    for (int k = 0; k < 128; ++k) {
        const unsigned long long* wp =
            reinterpret_cast<const unsigned long long*>(Ws + k * 128 + tx * 8);
        const unsigned long long w0 = wp[0];
        const unsigned long long w1 = wp[1];
        const unsigned long long w2 = wp[2];
        const unsigned long long w3 = wp[3];
#pragma unroll
        for (int r = 0; r < 8; ++r) {
            const float a = a_base[r * 128 + k];
            const unsigned long long aa = pack2(a, a);
            fma2(acc[r][0], aa, w0);
            fma2(acc[r][1], aa, w1);
            fma2(acc[r][2], aa, w2);
            fma2(acc[r][3], aa, w3);
        }
    }

#pragma unroll
    for (int r = 0; r < 8; ++r) {
        const long gr = row0 + ty * 8 + r;
        if (gr >= total_rows) continue;
        float o[8];
#pragma unroll
        for (int cp = 0; cp < 4; ++cp)
            unpack2(acc[r][cp], o[2 * cp], o[2 * cp + 1]);
        float4* op = reinterpret_cast<float4*>(g_y + gr * C_DIM + tx * 8);
        op[0] = make_float4(o[0], o[1], o[2], o[3]);
        op[1] = make_float4(o[4], o[5], o[6], o[7]);
    }
}

// ---------------------------------------------------------------------------
// Gather: out[b,n,:] = relu( bias + sum_e val_e * y[b, col_e, :] )
// One warp per row; lane owns 4 channels (float4). Edge records broadcast
// via shfl. 64 rows per CTA (8 warps x 8 rows), blockIdx.y = batch.
// ---------------------------------------------------------------------------
__global__ void __launch_bounds__(256)
gather_kernel(const float* __restrict__ bias,
              float*       __restrict__ out,
              int N) {
    const int lane = threadIdx.x & 31;
    const int warp = threadIdx.x >> 5;
    const int b    = blockIdx.y;

    const float4* yb    = reinterpret_cast<const float4*>(g_y) + (size_t)b * N * 32;
    const float4  bias4 = __ldg(reinterpret_cast<const float4*>(bias) + lane);

    const int n_base = blockIdx.x * 64;

#pragma unroll 1
    for (int i = 0; i < 8; ++i) {
        const int n = n_base + warp * 8 + i;
        if (n >= N) return;

        const int st = __ldg(&g_off[n]);
        const int en = __ldg(&g_off[n + 1]);

        float4 a0 = make_float4(0.f, 0.f, 0.f, 0.f);
        float4 a1 = make_float4(0.f, 0.f, 0.f, 0.f);

        for (int base = st; base < en; base += 32) {
            const int m = min(32, en - base);
            unsigned long long pk = 0;
            if (lane < m) pk = __ldg(&g_ebuf[base + lane]);

            int j = 0;
            for (; j + 1 < m; j += 2) {
                const unsigned long long p0 = __shfl_sync(0xffffffffu, pk, j);
                const unsigned long long p1 = __shfl_sync(0xffffffffu, pk, j + 1);
                const int   c0 = (int)(p0 & 0xffffffffu);
                const int   c1 = (int)(p1 & 0xffffffffu);
                const float v0 = __uint_as_float((unsigned)(p0 >> 32));
                const float v1 = __uint_as_float((unsigned)(p1 >> 32));
                const float4 x0 = __ldg(yb + (size_t)c0 * 32 + lane);
                const float4 x1 = __ldg(yb + (size_t)c1 * 32 + lane);
                a0.x = fmaf(v0, x0.x, a0.x); a0.y = fmaf(v0, x0.y, a0.y);
                a0.z = fmaf(v0, x0.z, a0.z); a0.w = fmaf(v0, x0.w, a0.w);
                a1.x = fmaf(v1, x1.x, a1.x); a1.y = fmaf(v1, x1.y, a1.y);
                a1.z = fmaf(v1, x1.z, a1.z); a1.w = fmaf(v1, x1.w, a1.w);
            }
            if (j < m) {
                const unsigned long long p0 = __shfl_sync(0xffffffffu, pk, j);
                const int   c0 = (int)(p0 & 0xffffffffu);
                const float v0 = __uint_as_float((unsigned)(p0 >> 32));
                const float4 x0 = __ldg(yb + (size_t)c0 * 32 + lane);
                a0.x = fmaf(v0, x0.x, a0.x); a0.y = fmaf(v0, x0.y, a0.y);
                a0.z = fmaf(v0, x0.z, a0.z); a0.w = fmaf(v0, x0.w, a0.w);
            }
        }

        float4 r;
        r.x = fmaxf(a0.x + a1.x + bias4.x, 0.f);
        r.y = fmaxf(a0.y + a1.y + bias4.y, 0.f);
        r.z = fmaxf(a0.z + a1.z + bias4.z, 0.f);
        r.w = fmaxf(a0.w + a1.w + bias4.w, 0.f);

        reinterpret_cast<float4*>(out)[((size_t)b * N + n) * 32 + lane] = r;
    }
}

// ---------------------------------------------------------------------------
// Launch
// ---------------------------------------------------------------------------
extern "C" void kernel_launch(void* const* d_in, const int* in_sizes, int n_in,
                              void* d_out, int out_size) {
    const float* x    = (const float*)d_in[0];
    const int*   er   = (const int*)  d_in[1];
    const int*   ec   = (const int*)  d_in[2];
    const float* ev   = (const float*)d_in[3];
    const float* W    = (const float*)d_in[4];
    const float* bias = (const float*)d_in[5];
    float*       out  = (float*)d_out;

    const int E  = in_sizes[1];
    const int C  = in_sizes[5];            // 128
    const int BN = in_sizes[0] / C;        // B*N
    const int N  = N_NODES;
    const int B  = BN / N;

    // 1) CSR build
    zero_deg_kernel<<<(N + 255) / 256, 256>>>(N);
    hist_kernel<<<(E + 255) / 256, 256>>>(er, E);
    scan_kernel<<<1, 1024>>>(N);
    scatter_kernel<<<(E + 255) / 256, 256>>>(er, ec, ev, E);

    // 2) y = x @ W
    cudaFuncSetAttribute(gemm_kernel,
                         cudaFuncAttributeMaxDynamicSharedMemorySize, 131072);
    gemm_kernel<<<(BN + 127) / 128, 256, 131072>>>(x, W, BN);

    // 3) gather + bias + relu
    dim3 ggrid((N + 63) / 64, B);
    gather_kernel<<<ggrid, 256>>>(bias, out, N);
}